// round 4
// baseline (speedup 1.0000x reference)
#include <cuda_runtime.h>
#include <math_constants.h>

// out[i] = (-pi^2 - (P*pi)^2 + a^2) * sin(pi*x0) * sin(P*pi*x1), P = 1
// HBM-bound streaming kernel: 12 B/element, ~201 MB total traffic.

#define PI_F 3.14159265358979323846f

__global__ void __launch_bounds__(256)
helm_kernel(const float4* __restrict__ in,   // [N/2] float4 = pairs of (x0,x1)
            const float* __restrict__ a,
            float4* __restrict__ out,        // [N/4] float4 outputs
            int n4)                           // N/4
{
    int i = blockIdx.x * blockDim.x + threadIdx.x;
    if (i >= n4) return;

    float av = __ldg(a);
    // coef = -pi^2 - pi^2 + a^2
    float coef = fmaf(av, av, -2.0f * PI_F * PI_F);

    // Two float4 loads = 4 input rows (x0,x1 interleaved)
    float4 p0 = in[2 * i];
    float4 p1 = in[2 * i + 1];

    float4 r;
    r.x = coef * __sinf(PI_F * p0.x) * __sinf(PI_F * p0.y);
    r.y = coef * __sinf(PI_F * p0.z) * __sinf(PI_F * p0.w);
    r.z = coef * __sinf(PI_F * p1.x) * __sinf(PI_F * p1.y);
    r.w = coef * __sinf(PI_F * p1.z) * __sinf(PI_F * p1.w);

    out[i] = r;
}

extern "C" void kernel_launch(void* const* d_in, const int* in_sizes, int n_in,
                              void* d_out, int out_size)
{
    const float* input = (const float*)d_in[0];   // [N, 2] flattened, N*2 floats
    const float* a     = (const float*)d_in[1];   // [1]
    float* out         = (float*)d_out;           // [N, 1]

    int n  = in_sizes[0] / 2;   // number of rows, 16777216
    int n4 = n / 4;             // 4194304 (N divisible by 4)

    int threads = 256;
    int blocks  = (n4 + threads - 1) / threads;

    helm_kernel<<<blocks, threads>>>(
        (const float4*)input, a, (float4*)out, n4);
}